// round 7
// baseline (speedup 1.0000x reference)
#include <cuda_runtime.h>
#include <cuda_bf16.h>
#include <math_constants.h>
#include <cstdint>

// ---------------------------------------------------------------------------
// MultiHeadAttention: x[2,2048,2048] fp32, 4x W[2048,2048]
// Round 6: GEMM -> cp.async 2-stage pipeline, 64x64 warp tiles, inputs
//          pre-rounded to tf32 (RNA) by producers. Attention as round 5.
// ---------------------------------------------------------------------------

#define BATCH   2
#define SEQ     2048
#define HID     2048
#define NH      16
#define HD      128
#define MTOT    (BATCH * SEQ)          // 4096

// scratch
__device__ float g_X[MTOT * HID];          // tf32-rounded x
__device__ float g_Q[MTOT * HID];
__device__ float g_K[MTOT * HID];
__device__ float g_V[MTOT * HID];
__device__ float g_A[MTOT * HID];          // attn out, tf32-rounded
__device__ float g_WT[4ull * HID * HID];   // transposed weights [N,K], tf32-rounded

// ---------------------------------------------------------------------------
__device__ __forceinline__ uint32_t f2tf32(float x) {
    uint32_t r;
    asm("cvt.rna.tf32.f32 %0, %1;" : "=r"(r) : "f"(x));
    return r;
}

__device__ __forceinline__ void mma_tf32(float* d, const uint32_t* a, const uint32_t* b) {
    asm volatile(
        "mma.sync.aligned.m16n8k8.row.col.f32.tf32.tf32.f32 "
        "{%0,%1,%2,%3}, {%4,%5,%6,%7}, {%8,%9}, {%0,%1,%2,%3};"
        : "+f"(d[0]), "+f"(d[1]), "+f"(d[2]), "+f"(d[3])
        : "r"(a[0]), "r"(a[1]), "r"(a[2]), "r"(a[3]), "r"(b[0]), "r"(b[1]));
}

__device__ __forceinline__ void cp16(uint32_t dst, const void* src) {
    asm volatile("cp.async.cg.shared.global [%0], [%1], 16;" :: "r"(dst), "l"(src));
}

// swizzled smem indexers (uint32 element index) for attention
__device__ __forceinline__ int swz128(int row, int col) {
    return row * 128 + (((((col >> 2) ^ row) & 7) | ((col >> 2) & ~7)) << 2) + (col & 3);
}
__device__ __forceinline__ int swz64(int row, int col) {
    return row * 64 + (((((col >> 2) ^ row) & 7) | ((col >> 2) & ~7)) << 2) + (col & 3);
}

// ---------------------------------------------------------------------------
// x -> tf32-rounded copy
// ---------------------------------------------------------------------------
__global__ __launch_bounds__(256)
void round_tf32_kernel(const float* __restrict__ in, float* __restrict__ out)
{
    const int i = (blockIdx.x * 256 + threadIdx.x) * 4;
    float4 v = *(const float4*)&in[i];
    uint4 u = make_uint4(f2tf32(v.x), f2tf32(v.y), f2tf32(v.z), f2tf32(v.w));
    *(uint4*)&out[i] = u;
}

// ---------------------------------------------------------------------------
// Weight transpose + tf32 rounding: Wt[n, k] = tf32(W[k, n])
// ---------------------------------------------------------------------------
__global__ __launch_bounds__(256)
void transpose2048(const float* __restrict__ W, float* __restrict__ Wt)
{
    __shared__ float tile[32][33];
    const int bx = blockIdx.x * 32;
    const int by = blockIdx.y * 32;
    const int tx = threadIdx.x, ty = threadIdx.y;

    for (int i = ty; i < 32; i += 8)
        tile[i][tx] = W[(size_t)(by + i) * HID + bx + tx];
    __syncthreads();
    for (int i = ty; i < 32; i += 8)
        Wt[(size_t)(bx + i) * HID + by + tx] = __uint_as_float(f2tf32(tile[tx][i]));
}

// ---------------------------------------------------------------------------
// Pipelined tf32 mma GEMM: C[4096,2048] = A[4096,2048] * Bt[2048,2048]^T
// A, Bt pre-rounded to tf32. CTA 128x128x32, 128 thr, 4 warps of 64x64.
// 2-stage cp.async double buffer. permute=1: fused head transpose on store.
// ---------------------------------------------------------------------------
#define TBM 128
#define TBN 128
#define TBK 32
#define KCHUNKS (HID / TBK)            // 64
#define SROW 36                        // smem row stride (u32)
#define STG  (TBM * SROW)              // 4608 u32 per matrix per stage

__global__ __launch_bounds__(128, 2)
void gemm_tf32_pipe(const float* __restrict__ A, const float* __restrict__ Bt,
                    float* __restrict__ C, int permute)
{
    extern __shared__ uint32_t dsm[];  // [A0|A1|B0|B1] = 4*4608 u32 = 72KB

    const int t    = threadIdx.x;
    const int wid  = t >> 5;
    const int lane = t & 31;
    const int grp  = lane >> 2;
    const int tid4 = lane & 3;
    const int m0   = blockIdx.y * TBM;
    const int n0   = blockIdx.x * TBN;
    const int wm   = (wid & 1) * 64;
    const int wn   = (wid >> 1) * 64;

    const uint32_t sbase = (uint32_t)__cvta_generic_to_shared(dsm);

    // loader mapping: pass p -> row = p*16 + (t>>3), float4 col = t&7
    const int lr = t >> 3;
    const int c4 = t & 7;
    const float* Ab = A  + (size_t)(m0 + lr) * HID + c4 * 4;
    const float* Bb = Bt + (size_t)(n0 + lr) * HID + c4 * 4;

    float acc[4][8][4];
#pragma unroll
    for (int mt = 0; mt < 4; mt++)
#pragma unroll
        for (int nt = 0; nt < 8; nt++)
#pragma unroll
            for (int r = 0; r < 4; r++) acc[mt][nt][r] = 0.f;

#define LOAD_STAGE(st, kk) do {                                               \
    const uint32_t dA = sbase + ((st) * STG + lr * SROW + c4 * 4) * 4;        \
    const uint32_t dB = dA + 2 * STG * 4;                                     \
    _Pragma("unroll")                                                         \
    for (int p = 0; p < 8; p++) {                                             \
        cp16(dA + p * 16 * SROW * 4, Ab + (size_t)p * 16 * HID + (kk));       \
        cp16(dB + p * 16 * SROW * 4, Bb + (size_t)p * 16 * HID + (kk));       \
    }                                                                         \
    asm volatile("cp.async.commit_group;");                                   \
} while (0)

    LOAD_STAGE(0, 0);

    for (int c = 0; c < KCHUNKS; ++c) {
        if (c + 1 < KCHUNKS) {
            LOAD_STAGE((c + 1) & 1, (c + 1) * TBK);
            asm volatile("cp.async.wait_group 1;");
        } else {
            asm volatile("cp.async.wait_group 0;");
        }
        __syncthreads();

        const uint32_t* cA = dsm + (c & 1) * STG;
        const uint32_t* cB = cA + 2 * STG;

#pragma unroll
        for (int ks = 0; ks < 4; ks++) {
            const int k0 = ks * 8;
            uint32_t af[4][4], bf[8][2];
#pragma unroll
            for (int mt = 0; mt < 4; mt++) {
                const int r = wm + mt * 16 + grp;
                af[mt][0] = cA[r * SROW + k0 + tid4];
                af[mt][1] = cA[(r + 8) * SROW + k0 + tid4];
                af[mt][2] = cA[r * SROW + k0 + tid4 + 4];
                af[mt][3] = cA[(r + 8) * SROW + k0 + tid4 + 4];
            }
#pragma unroll
            for (int nt = 0; nt < 8; nt++) {
                const int n = wn + nt * 8 + grp;
                bf[nt][0] = cB[n * SROW + k0 + tid4];
                bf[nt][1] = cB[n * SROW + k0 + tid4 + 4];
            }
#pragma unroll
            for (int mt = 0; mt < 4; mt++)
#pragma unroll
                for (int nt = 0; nt < 8; nt++)
                    mma_tf32(acc[mt][nt], af[mt], bf[nt]);
        }
        __syncthreads();
    }

    // epilogue
#pragma unroll
    for (int mt = 0; mt < 4; mt++) {
#pragma unroll
        for (int nt = 0; nt < 8; nt++) {
            const int row0 = m0 + wm + mt * 16 + grp;
            const int col  = n0 + wn + nt * 8 + tid4 * 2;
#pragma unroll
            for (int h = 0; h < 2; h++) {
                const int row = row0 + h * 8;
                float2 v = make_float2(acc[mt][nt][h * 2], acc[mt][nt][h * 2 + 1]);
                if (permute) {
                    const int b = row >> 11, s = row & 2047;
                    const int hh = col >> 7, dc = col & 127;
                    *(float2*)&C[((size_t)((b * NH + hh) * SEQ + s)) * HD + dc] = v;
                } else {
                    *(float2*)&C[(size_t)row * HID + col] = v;
                }
            }
        }
    }
}
#define GEMM_SMEM_BYTES (4 * STG * 4)   // 73728

// ---------------------------------------------------------------------------
// Tensor-core flash attention (round 5, passing). Epilogue now rounds to tf32.
// ---------------------------------------------------------------------------
__global__ __launch_bounds__(128)
void attn_mma_kernel(const float* __restrict__ Q, const float* __restrict__ K,
                     const float* __restrict__ V, float* __restrict__ O)
{
    extern __shared__ uint32_t dsm[];
    uint32_t* sQ  = dsm;            // 8192  u32
    uint32_t* sKV = dsm + 8192;     // 8192  u32 (K or V^T)
    uint32_t* sP  = dsm + 16384;    // 4096  u32

    const int t    = threadIdx.x;
    const int w    = t >> 5;
    const int lane = t & 31;
    const int grp  = lane >> 2;
    const int tid4 = lane & 3;
    const int qb   = blockIdx.x;
    const int bh   = blockIdx.y;
    const float scale = 0.08838834764831845f;

    const float* Qb = Q + ((size_t)bh * SEQ + qb * 64) * HD;
    const float* Kb = K + (size_t)bh * SEQ * HD;
    const float* Vb = V + (size_t)bh * SEQ * HD;

#pragma unroll
    for (int p = 0; p < 16; p++) {
        const int row = p * 4 + w;
        float4 v = *(const float4*)&Qb[(size_t)row * HD + lane * 4];
        uint32_t* d = &sQ[row * 128 + ((lane ^ (row & 7)) << 2)];
        d[0] = f2tf32(v.x * scale); d[1] = f2tf32(v.y * scale);
        d[2] = f2tf32(v.z * scale); d[3] = f2tf32(v.w * scale);
    }

    const int r0 = w * 16 + grp;
    float m0 = -CUDART_INF_F, m1 = -CUDART_INF_F;
    float l0 = 0.f, l1 = 0.f;
    float o[16][4];
#pragma unroll
    for (int nt = 0; nt < 16; nt++)
#pragma unroll
        for (int r = 0; r < 4; r++) o[nt][r] = 0.f;

    for (int kb = 0; kb <= qb; kb++) {
#pragma unroll
        for (int p = 0; p < 16; p++) {
            const int row = p * 4 + w;
            float4 v = *(const float4*)&Kb[(size_t)(kb * 64 + row) * HD + lane * 4];
            uint32_t* d = &sKV[row * 128 + ((lane ^ (row & 7)) << 2)];
            d[0] = f2tf32(v.x); d[1] = f2tf32(v.y);
            d[2] = f2tf32(v.z); d[3] = f2tf32(v.w);
        }
        __syncthreads();

        float s[8][4];
#pragma unroll
        for (int nt = 0; nt < 8; nt++)
#pragma unroll
            for (int r = 0; r < 4; r++) s[nt][r] = 0.f;

#pragma unroll
        for (int ks = 0; ks < 16; ks++) {
            const int k0 = ks * 8;
            uint32_t a[4];
            a[0] = sQ[swz128(r0,     k0 + tid4)];
            a[1] = sQ[swz128(r0 + 8, k0 + tid4)];
            a[2] = sQ[swz128(r0,     k0 + tid4 + 4)];
            a[3] = sQ[swz128(r0 + 8, k0 + tid4 + 4)];
#pragma unroll
            for (int nt = 0; nt < 8; nt++) {
                uint32_t b[2];
                b[0] = sKV[swz128(nt * 8 + grp, k0 + tid4)];
                b[1] = sKV[swz128(nt * 8 + grp, k0 + tid4 + 4)];
                mma_tf32(s[nt], a, b);
            }
        }
        __syncthreads();

        if (kb == qb) {
            const int rg0 = qb * 64 + r0;
            const int rg1 = rg0 + 8;
#pragma unroll
            for (int nt = 0; nt < 8; nt++) {
                const int c0 = kb * 64 + nt * 8 + 2 * tid4;
                if (c0     > rg0) s[nt][0] = -CUDART_INF_F;
                if (c0 + 1 > rg0) s[nt][1] = -CUDART_INF_F;
                if (c0     > rg1) s[nt][2] = -CUDART_INF_F;
                if (c0 + 1 > rg1) s[nt][3] = -CUDART_INF_F;
            }
        }

        {
            const int kv = lane + 32 * (w & 1);
#pragma unroll
            for (int p = 0; p < 16; p++) {
                const int hc = 2 * p + (w >> 1);
                float4 v = *(const float4*)&Vb[(size_t)(kb * 64 + kv) * HD + hc * 4];
                const int hd0 = 4 * hc;
                sKV[(hd0    ) * 64 + ((((kv >> 2) ^ ( hd0      & 7)) << 2)) + (kv & 3)] = f2tf32(v.x);
                sKV[(hd0 + 1) * 64 + ((((kv >> 2) ^ ((hd0 + 1) & 7)) << 2)) + (kv & 3)] = f2tf32(v.y);
                sKV[(hd0 + 2) * 64 + ((((kv >> 2) ^ ((hd0 + 2) & 7)) << 2)) + (kv & 3)] = f2tf32(v.z);
                sKV[(hd0 + 3) * 64 + ((((kv >> 2) ^ ((hd0 + 3) & 7)) << 2)) + (kv & 3)] = f2tf32(v.w);
            }
        }

        float rm0 = -CUDART_INF_F, rm1 = -CUDART_INF_F;
#pragma unroll
        for (int nt = 0; nt < 8; nt++) {
            rm0 = fmaxf(rm0, fmaxf(s[nt][0], s[nt][1]));
            rm1 = fmaxf(rm1, fmaxf(s[nt][2], s[nt][3]));
        }
        rm0 = fmaxf(rm0, __shfl_xor_sync(0xffffffffu, rm0, 1));
        rm0 = fmaxf(rm0, __shfl_xor_sync(0xffffffffu, rm0, 2));
        rm1 = fmaxf(rm1, __shfl_xor_sync(0xffffffffu, rm1, 1));
        rm1 = fmaxf(rm1, __shfl_xor_sync(0xffffffffu, rm1, 2));

        const float mn0 = fmaxf(m0, rm0);
        const float mn1 = fmaxf(m1, rm1);
        const float cf0 = __expf(m0 - mn0);
        const float cf1 = __expf(m1 - mn1);
        m0 = mn0; m1 = mn1;

        float ps0 = 0.f, ps1 = 0.f;
#pragma unroll
        for (int nt = 0; nt < 8; nt++) {
            const float p00 = __expf(s[nt][0] - m0);
            const float p01 = __expf(s[nt][1] - m0);
            const float p10 = __expf(s[nt][2] - m1);
            const float p11 = __expf(s[nt][3] - m1);
            ps0 += p00 + p01;
            ps1 += p10 + p11;
            uint2 u0 = make_uint2(f2tf32(p00), f2tf32(p01));
            uint2 u1 = make_uint2(f2tf32(p10), f2tf32(p11));
            *(uint2*)&sP[swz64(r0,     nt * 8 + 2 * tid4)] = u0;
            *(uint2*)&sP[swz64(r0 + 8, nt * 8 + 2 * tid4)] = u1;
        }
        ps0 += __shfl_xor_sync(0xffffffffu, ps0, 1);
        ps0 += __shfl_xor_sync(0xffffffffu, ps0, 2);
        ps1 += __shfl_xor_sync(0xffffffffu, ps1, 1);
        ps1 += __shfl_xor_sync(0xffffffffu, ps1, 2);
        l0 = l0 * cf0 + ps0;
        l1 = l1 * cf1 + ps1;

#pragma unroll
        for (int nt = 0; nt < 16; nt++) {
            o[nt][0] *= cf0; o[nt][1] *= cf0;
            o[nt][2] *= cf1; o[nt][3] *= cf1;
        }

        __syncthreads();

#pragma unroll
        for (int kt = 0; kt < 8; kt++) {
            const int k0 = kt * 8;
            uint32_t a[4];
            a[0] = sP[swz64(r0,     k0 + tid4)];
            a[1] = sP[swz64(r0 + 8, k0 + tid4)];
            a[2] = sP[swz64(r0,     k0 + tid4 + 4)];
            a[3] = sP[swz64(r0 + 8, k0 + tid4 + 4)];
#pragma unroll
            for (int nt = 0; nt < 16; nt++) {
                uint32_t b[2];
                b[0] = sKV[swz64(nt * 8 + grp, k0 + tid4)];
                b[1] = sKV[swz64(nt * 8 + grp, k0 + tid4 + 4)];
                mma_tf32(o[nt], a, b);
            }
        }
        __syncthreads();
    }

    // epilogue: normalize, round to tf32 (feeds pre-rounded Wo GEMM), store
    const int bb = bh >> 4, hh = bh & 15;
    const float i0 = 1.f / l0;
    const float i1 = 1.f / l1;
    const int sg = qb * 64 + r0;
#pragma unroll
    for (int nt = 0; nt < 16; nt++) {
        const int col = hh * 128 + nt * 8 + 2 * tid4;
        uint2 v0 = make_uint2(f2tf32(o[nt][0] * i0), f2tf32(o[nt][1] * i0));
        uint2 v1 = make_uint2(f2tf32(o[nt][2] * i1), f2tf32(o[nt][3] * i1));
        *(uint2*)&O[((size_t)(bb * SEQ + sg    )) * HID + col] = v0;
        *(uint2*)&O[((size_t)(bb * SEQ + sg + 8)) * HID + col] = v1;
    }
}

#define ATTN_SMEM_BYTES (20480 * 4)   // 80 KB

// ---------------------------------------------------------------------------
extern "C" void kernel_launch(void* const* d_in, const int* in_sizes, int n_in,
                              void* d_out, int out_size)
{
    const float* x  = (const float*)d_in[0];
    const float* Wq = (const float*)d_in[1];
    const float* Wk = (const float*)d_in[2];
    const float* Wv = (const float*)d_in[3];
    const float* Wo = (const float*)d_in[4];

    float *Xp, *Qp, *Kp, *Vp, *Ap, *WTp;
    cudaGetSymbolAddress((void**)&Xp,  g_X);
    cudaGetSymbolAddress((void**)&Qp,  g_Q);
    cudaGetSymbolAddress((void**)&Kp,  g_K);
    cudaGetSymbolAddress((void**)&Vp,  g_V);
    cudaGetSymbolAddress((void**)&Ap,  g_A);
    cudaGetSymbolAddress((void**)&WTp, g_WT);

    cudaFuncSetAttribute(attn_mma_kernel,
                         cudaFuncAttributeMaxDynamicSharedMemorySize,
                         ATTN_SMEM_BYTES);
    cudaFuncSetAttribute(gemm_tf32_pipe,
                         cudaFuncAttributeMaxDynamicSharedMemorySize,
                         GEMM_SMEM_BYTES);

    const size_t WSZ = (size_t)HID * HID;

    round_tf32_kernel<<<MTOT * HID / 1024, 256>>>(x, Xp);

    dim3 tg(64, 64), tb(32, 8);
    transpose2048<<<tg, tb>>>(Wq, WTp + 0 * WSZ);
    transpose2048<<<tg, tb>>>(Wk, WTp + 1 * WSZ);
    transpose2048<<<tg, tb>>>(Wv, WTp + 2 * WSZ);
    transpose2048<<<tg, tb>>>(Wo, WTp + 3 * WSZ);

    dim3 gg(HID / TBN, MTOT / TBM);   // (16, 32)
    gemm_tf32_pipe<<<gg, 128, GEMM_SMEM_BYTES>>>(Xp, WTp + 0 * WSZ, Qp, 1);
    gemm_tf32_pipe<<<gg, 128, GEMM_SMEM_BYTES>>>(Xp, WTp + 1 * WSZ, Kp, 1);
    gemm_tf32_pipe<<<gg, 128, GEMM_SMEM_BYTES>>>(Xp, WTp + 2 * WSZ, Vp, 1);

    attn_mma_kernel<<<dim3(SEQ / 64, BATCH * NH), 128, ATTN_SMEM_BYTES>>>(Qp, Kp, Vp, Ap);

    gemm_tf32_pipe<<<gg, 128, GEMM_SMEM_BYTES>>>(Ap, WTp + 3 * WSZ, (float*)d_out, 0);
}

// round 8
// speedup vs baseline: 1.8492x; 1.8492x over previous
#include <cuda_runtime.h>
#include <cuda_fp16.h>
#include <math_constants.h>
#include <cstdint>

// ---------------------------------------------------------------------------
// MultiHeadAttention: x[2,2048,2048] fp32, 4x W[2048,2048]
// Round 8: everything on mma.sync m16n8k16 fp16 (fp32 accum). Halves the
//          HMMA instruction count vs tf32 k8 at identical rounding eps (2^-11).
// ---------------------------------------------------------------------------

#define BATCH   2
#define SEQ     2048
#define HID     2048
#define NH      16
#define HD      128
#define MTOT    (BATCH * SEQ)          // 4096

// scratch (all fp16 operands)
__device__ __half g_X[MTOT * HID];
__device__ __half g_Q[MTOT * HID];
__device__ __half g_K[MTOT * HID];
__device__ __half g_V[MTOT * HID];
__device__ __half g_A[MTOT * HID];
__device__ __half g_WT[4ull * HID * HID];   // transposed weights [N,K]

// ---------------------------------------------------------------------------
__device__ __forceinline__ void mma_f16(float* d, const uint32_t* a, const uint32_t* b) {
    asm volatile(
        "mma.sync.aligned.m16n8k16.row.col.f32.f16.f16.f32 "
        "{%0,%1,%2,%3}, {%4,%5,%6,%7}, {%8,%9}, {%0,%1,%2,%3};"
        : "+f"(d[0]), "+f"(d[1]), "+f"(d[2]), "+f"(d[3])
        : "r"(a[0]), "r"(a[1]), "r"(a[2]), "r"(a[3]), "r"(b[0]), "r"(b[1]));
}

__device__ __forceinline__ uint32_t h2u(__half2 h) {
    return *reinterpret_cast<uint32_t*>(&h);
}

__device__ __forceinline__ void cp16(uint32_t dst, const void* src) {
    asm volatile("cp.async.cg.shared.global [%0], [%1], 16;" :: "r"(dst), "l"(src));
}

// ---------------------------------------------------------------------------
// Weight transpose + fp16: Wt[n,k] = half(W[k,n] * scale)
// ---------------------------------------------------------------------------
__global__ __launch_bounds__(256)
void transpose2048h(const float* __restrict__ W, __half* __restrict__ Wt, float scale)
{
    __shared__ float tile[32][33];
    const int bx = blockIdx.x * 32;
    const int by = blockIdx.y * 32;
    const int tx = threadIdx.x, ty = threadIdx.y;

    for (int i = ty; i < 32; i += 8)
        tile[i][tx] = W[(size_t)(by + i) * HID + bx + tx];
    __syncthreads();
    for (int i = ty; i < 32; i += 8)
        Wt[(size_t)(bx + i) * HID + by + tx] = __float2half_rn(tile[tx][i] * scale);
}

// ---------------------------------------------------------------------------
// x -> fp16
// ---------------------------------------------------------------------------
__global__ __launch_bounds__(256)
void round_x_kernel(const float* __restrict__ in, __half* __restrict__ out)
{
    const int i = (blockIdx.x * 256 + threadIdx.x) * 8;
    float4 v0 = *(const float4*)&in[i];
    float4 v1 = *(const float4*)&in[i + 4];
    uint4 u;
    u.x = h2u(__floats2half2_rn(v0.x, v0.y));
    u.y = h2u(__floats2half2_rn(v0.z, v0.w));
    u.z = h2u(__floats2half2_rn(v1.x, v1.y));
    u.w = h2u(__floats2half2_rn(v1.z, v1.w));
    *(uint4*)&out[i] = u;
}

// ---------------------------------------------------------------------------
// fp16 mma GEMM: C[4096,2048] = A[4096,2048] * Bt[2048,2048]^T
// Bt [N,K] halfs. CTA 128x128x32(half-K), 128 thr, 4 warps 64x64.
// 2-stage cp.async. gridDim.z selects (Bt, C) for fused QKV.
// permute=1: half output into [B*NH,S,HD]; permute=0: f32 output [M,HID].
// ---------------------------------------------------------------------------
#define TBM 128
#define TBN 128
#define TBK 32                          // halfs per chunk
#define KCH (HID / TBK)                 // 64
#define SR2 20                          // half2 words per row (16 data + 4 pad)
#define STG (TBM * SR2)                 // 2560 words per matrix per stage

__global__ __launch_bounds__(128, 2)
void gemm_f16(const __half* __restrict__ A, const __half* __restrict__ BtBase,
              void* C0, void* C1, void* C2, int permute)
{
    __shared__ uint32_t dsm[4 * STG];   // A0 A1 B0 B1 = 40KB

    const __half* Bt = BtBase + (size_t)blockIdx.z * HID * HID;
    void* Cp = (blockIdx.z == 0) ? C0 : (blockIdx.z == 1 ? C1 : C2);

    const int t    = threadIdx.x;
    const int wid  = t >> 5;
    const int lane = t & 31;
    const int grp  = lane >> 2;
    const int tid4 = lane & 3;
    const int m0   = blockIdx.y * TBM;
    const int n0   = blockIdx.x * TBN;
    const int wm   = (wid & 1) * 64;
    const int wn   = (wid >> 1) * 64;

    const uint32_t sbase = (uint32_t)__cvta_generic_to_shared(dsm);

    // loader: lr = t>>2 (0..31), c16 = t&3 (16B unit), 4 passes of 32 rows
    const int lr  = t >> 2;
    const int c16 = t & 3;
    const __half* Ab = A  + (size_t)(m0 + lr) * HID + c16 * 8;
    const __half* Bb = Bt + (size_t)(n0 + lr) * HID + c16 * 8;

    float acc[4][8][4];
#pragma unroll
    for (int mt = 0; mt < 4; mt++)
#pragma unroll
        for (int nt = 0; nt < 8; nt++)
#pragma unroll
            for (int r = 0; r < 4; r++) acc[mt][nt][r] = 0.f;

#define LOAD_STAGE(st, kk) do {                                               \
    const uint32_t dA = sbase + ((st) * STG + lr * SR2 + c16 * 4) * 4;        \
    const uint32_t dB = dA + 2 * STG * 4;                                     \
    _Pragma("unroll")                                                         \
    for (int p = 0; p < 4; p++) {                                             \
        cp16(dA + p * 32 * SR2 * 4, Ab + (size_t)p * 32 * HID + (kk));        \
        cp16(dB + p * 32 * SR2 * 4, Bb + (size_t)p * 32 * HID + (kk));        \
    }                                                                         \
    asm volatile("cp.async.commit_group;");                                   \
} while (0)

    LOAD_STAGE(0, 0);

    for (int c = 0; c < KCH; ++c) {
        if (c + 1 < KCH) {
            LOAD_STAGE((c + 1) & 1, (c + 1) * TBK);
            asm volatile("cp.async.wait_group 1;");
        } else {
            asm volatile("cp.async.wait_group 0;");
        }
        __syncthreads();

        const uint32_t* cA = dsm + (c & 1) * STG;
        const uint32_t* cB = cA + 2 * STG;

#pragma unroll
        for (int ks = 0; ks < 2; ks++) {        // 2 x K=16 halfs
            const int k2 = ks * 8;
            uint32_t af[4][4], bf[8][2];
#pragma unroll
            for (int mt = 0; mt < 4; mt++) {
                const int r = wm + mt * 16 + grp;
                af[mt][0] = cA[r * SR2 + k2 + tid4];
                af[mt][1] = cA[(r + 8) * SR2 + k2 + tid4];
                af[mt][2] = cA[r * SR2 + k2 + tid4 + 4];
                af[mt][3] = cA[(r + 8) * SR2 + k2 + tid4 + 4];
            }
#pragma unroll
            for (int nt = 0; nt < 8; nt++) {
                const int n = wn + nt * 8 + grp;
                bf[nt][0] = cB[n * SR2 + k2 + tid4];
                bf[nt][1] = cB[n * SR2 + k2 + tid4 + 4];
            }
#pragma unroll
            for (int mt = 0; mt < 4; mt++)
#pragma unroll
                for (int nt = 0; nt < 8; nt++)
                    mma_f16(acc[mt][nt], af[mt], bf[nt]);
        }
        __syncthreads();
    }

    // epilogue
#pragma unroll
    for (int mt = 0; mt < 4; mt++) {
#pragma unroll
        for (int nt = 0; nt < 8; nt++) {
            const int row0 = m0 + wm + mt * 16 + grp;
            const int col  = n0 + wn + nt * 8 + tid4 * 2;
#pragma unroll
            for (int h = 0; h < 2; h++) {
                const int row = row0 + h * 8;
                if (permute) {
                    const int b = row >> 11, s = row & 2047;
                    const int hh = col >> 7, dc = col & 127;
                    __half* Ch = (__half*)Cp;
                    *(__half2*)&Ch[((size_t)((b * NH + hh) * SEQ + s)) * HD + dc] =
                        __floats2half2_rn(acc[mt][nt][h * 2], acc[mt][nt][h * 2 + 1]);
                } else {
                    float* Cf = (float*)Cp;
                    *(float2*)&Cf[(size_t)row * HID + col] =
                        make_float2(acc[mt][nt][h * 2], acc[mt][nt][h * 2 + 1]);
                }
            }
        }
    }
}

// ---------------------------------------------------------------------------
// fp16 tensor-core flash attention. Q,K,V: half [B*NH, S, HD] (Q pre-scaled
// via Wq). Out: g_A half [B,S,HID]. CTA 64 q-rows, 128 thr, KV tile 64.
// Static smem 45KB: sQ[64][68] | sKV(K[64][68] / VT[128][36]) | sP[64][36].
// ---------------------------------------------------------------------------
__global__ __launch_bounds__(128)
void attn_f16_kernel(const __half* __restrict__ Q, const __half* __restrict__ K,
                     const __half* __restrict__ V, __half* __restrict__ O)
{
    __shared__ uint32_t sQ[64 * 68];
    __shared__ uint32_t sKV[128 * 36];
    __shared__ uint32_t sP[64 * 36];

    const int t    = threadIdx.x;
    const int w    = t >> 5;
    const int lane = t & 31;
    const int grp  = lane >> 2;
    const int tid4 = lane & 3;
    const int qb   = blockIdx.x;
    const int bh   = blockIdx.y;

    const __half* Qb = Q + ((size_t)bh * SEQ + qb * 64) * HD;
    const __half* Kb = K + (size_t)bh * SEQ * HD;
    const __half* Vb = V + (size_t)bh * SEQ * HD;

    // ---- load Q tile (straight half copy; scale folded into Wq) ----
#pragma unroll
    for (int p = 0; p < 8; p++) {
        const int row = p * 8 + (t >> 4);
        const int c16 = t & 15;
        uint4 v = *(const uint4*)&Qb[(size_t)row * HD + c16 * 8];
        *(uint4*)&sQ[row * 68 + c16 * 4] = v;
    }

    const int r0 = w * 16 + grp;
    float m0 = -CUDART_INF_F, m1 = -CUDART_INF_F;
    float l0 = 0.f, l1 = 0.f;
    float o[16][4];
#pragma unroll
    for (int nt = 0; nt < 16; nt++)
#pragma unroll
        for (int r = 0; r < 4; r++) o[nt][r] = 0.f;

    for (int kb = 0; kb <= qb; kb++) {
        // ---- K tile [64][68] ----
#pragma unroll
        for (int p = 0; p < 8; p++) {
            const int row = p * 8 + (t >> 4);
            const int c16 = t & 15;
            uint4 v = *(const uint4*)&Kb[(size_t)(kb * 64 + row) * HD + c16 * 8];
            *(uint4*)&sKV[row * 68 + c16 * 4] = v;
        }
        __syncthreads();

        // ---- S = Q K^T : 8 ksteps of K=16 halfs ----
        float s[8][4];
#pragma unroll
        for (int nt = 0; nt < 8; nt++)
#pragma unroll
            for (int r = 0; r < 4; r++) s[nt][r] = 0.f;

#pragma unroll
        for (int ks = 0; ks < 8; ks++) {
            const int k2 = ks * 8;
            uint32_t a[4];
            a[0] = sQ[r0 * 68 + k2 + tid4];
            a[1] = sQ[(r0 + 8) * 68 + k2 + tid4];
            a[2] = sQ[r0 * 68 + k2 + tid4 + 4];
            a[3] = sQ[(r0 + 8) * 68 + k2 + tid4 + 4];
#pragma unroll
            for (int nt = 0; nt < 8; nt++) {
                uint32_t b[2];
                b[0] = sKV[(nt * 8 + grp) * 68 + k2 + tid4];
                b[1] = sKV[(nt * 8 + grp) * 68 + k2 + tid4 + 4];
                mma_f16(s[nt], a, b);
            }
        }
        __syncthreads();    // K consumed -> sKV reusable for V^T

        // ---- causal mask (diagonal tile) ----
        if (kb == qb) {
            const int rg0 = qb * 64 + r0;
            const int rg1 = rg0 + 8;
#pragma unroll
            for (int nt = 0; nt < 8; nt++) {
                const int c0 = kb * 64 + nt * 8 + 2 * tid4;
                if (c0     > rg0) s[nt][0] = -CUDART_INF_F;
                if (c0 + 1 > rg0) s[nt][1] = -CUDART_INF_F;
                if (c0     > rg1) s[nt][2] = -CUDART_INF_F;
                if (c0 + 1 > rg1) s[nt][3] = -CUDART_INF_F;
            }
        }

        // ---- V^T fill: word [d][kv2] = half2(V[2kv2][d], V[2kv2+1][d]) ----
#pragma unroll
        for (int p = 0; p < 4; p++) {
            const int id  = t + 128 * p;          // 0..511
            const int d0  = 8 * (id & 15);        // 0..120
            const int kv0 = 2 * (id >> 4);        // 0..62 even
            const __half* vr = Vb + (size_t)(kb * 64 + kv0) * HD + d0;
            uint4 ua = *(const uint4*)vr;
            uint4 ub = *(const uint4*)(vr + HD);
            const __half* ha = (const __half*)&ua;
            const __half* hb = (const __half*)&ub;
#pragma unroll
            for (int j = 0; j < 8; j++) {
                const int dj = (j + lane) & 7;    // lane-rotated to spread banks
                sKV[(d0 + dj) * 36 + (kv0 >> 1)] =
                    h2u(__halves2half2(ha[dj], hb[dj]));
            }
        }

        // ---- online softmax on fragments ----
        float rm0 = -CUDART_INF_F, rm1 = -CUDART_INF_F;
#pragma unroll
        for (int nt = 0; nt < 8; nt++) {
            rm0 = fmaxf(rm0, fmaxf(s[nt][0], s[nt][1]));
            rm1 = fmaxf(rm1, fmaxf(s[nt][2], s[nt][3]));
        }
        rm0 = fmaxf(rm0, __shfl_xor_sync(0xffffffffu, rm0, 1));
        rm0 = fmaxf(rm0, __shfl_xor_sync(0xffffffffu, rm0, 2));
        rm1 = fmaxf(rm1, __shfl_xor_sync(0xffffffffu, rm1, 1));
        rm1 = fmaxf(rm1, __shfl_xor_sync(0xffffffffu, rm1, 2));

        const float mn0 = fmaxf(m0, rm0);
        const float mn1 = fmaxf(m1, rm1);
        const float cf0 = __expf(m0 - mn0);
        const float cf1 = __expf(m1 - mn1);
        m0 = mn0; m1 = mn1;

        float ps0 = 0.f, ps1 = 0.f;
#pragma unroll
        for (int nt = 0; nt < 8; nt++) {
            const float p00 = __expf(s[nt][0] - m0);
            const float p01 = __expf(s[nt][1] - m0);
            const float p10 = __expf(s[nt][2] - m1);
            const float p11 = __expf(s[nt][3] - m1);
            ps0 += p00 + p01;
            ps1 += p10 + p11;
            sP[r0 * 36 + nt * 4 + tid4]       = h2u(__floats2half2_rn(p00, p01));
            sP[(r0 + 8) * 36 + nt * 4 + tid4] = h2u(__floats2half2_rn(p10, p11));
        }
        ps0 += __shfl_xor_sync(0xffffffffu, ps0, 1);
        ps0 += __shfl_xor_sync(0xffffffffu, ps0, 2);
        ps1 += __shfl_xor_sync(0xffffffffu, ps1, 1);
        ps1 += __shfl_xor_sync(0xffffffffu, ps1, 2);
        l0 = l0 * cf0 + ps0;
        l1 = l1 * cf1 + ps1;

#pragma unroll
        for (int nt = 0; nt < 16; nt++) {
            o[nt][0] *= cf0; o[nt][1] *= cf0;
            o[nt][2] *= cf1; o[nt][3] *= cf1;
        }

        __syncthreads();    // V^T + P visible

        // ---- O += P V : 4 ksteps of K=16 kv ----
#pragma unroll
        for (int kt = 0; kt < 4; kt++) {
            const int k2 = kt * 8;
            uint32_t a[4];
            a[0] = sP[r0 * 36 + k2 + tid4];
            a[1] = sP[(r0 + 8) * 36 + k2 + tid4];
            a[2] = sP[r0 * 36 + k2 + tid4 + 4];
            a[3] = sP[(r0 + 8) * 36 + k2 + tid4 + 4];
#pragma unroll
            for (int nt = 0; nt < 16; nt++) {
                uint32_t b[2];
                b[0] = sKV[(nt * 8 + grp) * 36 + k2 + tid4];
                b[1] = sKV[(nt * 8 + grp) * 36 + k2 + tid4 + 4];
                mma_f16(o[nt], a, b);
            }
        }
        __syncthreads();    // V^T consumed before next K store
    }

    // ---- epilogue: normalize, half output to [B,S,HID] ----
    const int bb = bh >> 4, hh = bh & 15;
    const float i0 = 1.f / l0;
    const float i1 = 1.f / l1;
    const int sg = qb * 64 + r0;
#pragma unroll
    for (int nt = 0; nt < 16; nt++) {
        const int col = hh * 128 + nt * 8 + 2 * tid4;
        *(__half2*)&O[((size_t)(bb * SEQ + sg)) * HID + col] =
            __floats2half2_rn(o[nt][0] * i0, o[nt][1] * i0);
        *(__half2*)&O[((size_t)(bb * SEQ + sg + 8)) * HID + col] =
            __floats2half2_rn(o[nt][2] * i1, o[nt][3] * i1);
    }
}

// ---------------------------------------------------------------------------
extern "C" void kernel_launch(void* const* d_in, const int* in_sizes, int n_in,
                              void* d_out, int out_size)
{
    const float* x  = (const float*)d_in[0];
    const float* Wq = (const float*)d_in[1];
    const float* Wk = (const float*)d_in[2];
    const float* Wv = (const float*)d_in[3];
    const float* Wo = (const float*)d_in[4];

    __half *Xp, *Qp, *Kp, *Vp, *Ap, *WTp;
    cudaGetSymbolAddress((void**)&Xp,  g_X);
    cudaGetSymbolAddress((void**)&Qp,  g_Q);
    cudaGetSymbolAddress((void**)&Kp,  g_K);
    cudaGetSymbolAddress((void**)&Vp,  g_V);
    cudaGetSymbolAddress((void**)&Ap,  g_A);
    cudaGetSymbolAddress((void**)&WTp, g_WT);

    const size_t WSZ = (size_t)HID * HID;
    const float qscale = 0.08838834764831845f;   // 1/sqrt(128), folded into Wq

    dim3 tg(64, 64), tb(32, 8);
    transpose2048h<<<tg, tb>>>(Wq, WTp + 0 * WSZ, qscale);
    transpose2048h<<<tg, tb>>>(Wk, WTp + 1 * WSZ, 1.0f);
    transpose2048h<<<tg, tb>>>(Wv, WTp + 2 * WSZ, 1.0f);
    transpose2048h<<<tg, tb>>>(Wo, WTp + 3 * WSZ, 1.0f);
    round_x_kernel<<<MTOT * HID / 2048, 256>>>(x, Xp);

    // fused QKV: gridDim.z picks weight + destination
    gemm_f16<<<dim3(HID / TBN, MTOT / TBM, 3), 128>>>(Xp, WTp, Qp, Kp, Vp, 1);

    attn_f16_kernel<<<dim3(SEQ / 64, BATCH * NH), 128>>>(Qp, Kp, Vp, Ap);

    gemm_f16<<<dim3(HID / TBN, MTOT / TBM, 1), 128>>>(Ap, WTp + 3 * WSZ,
                                                      d_out, nullptr, nullptr, 0);
}